// round 5
// baseline (speedup 1.0000x reference)
#include <cuda_runtime.h>

// ZBL pair energy + segment-sum into per-atom energies.
//
// Inputs (metadata order; JAX without x64 stores "int64" as int32):
//   d_in[0] Z               float32 [4]
//   d_in[1] r               float32 [E]          (E = 6,400,000)
//   d_in[2] per_atom_energy float32 [n_atoms,1]  (n_atoms = 100,000)
//   d_in[3] atom_types      int32   [n_atoms]
//   d_in[4] edge_index      int32   [2, E]
// Output: float32 [n_atoms, 1]

#define ZBL_QQ        7.1998225f        // 14.399645 * 0.5
#define ZBL_INV_A0    (1.0f / 0.4685f)
#define ZBL_INV_RMAX  (1.0f / 6.0f)
#define LOG2E         1.4426950408889634f

__device__ __forceinline__ float ex2_approx(float x) {
    float y;
    asm("ex2.approx.f32 %0, %1;" : "=f"(y) : "f"(x));
    return y;
}
__device__ __forceinline__ float rcp_approx(float x) {
    float y;
    asm("rcp.approx.f32 %0, %1;" : "=f"(y) : "f"(x));
    return y;
}

__global__ void init_out_kernel(const float* __restrict__ pae,
                                float* __restrict__ out, int n) {
    int i = blockIdx.x * blockDim.x + threadIdx.x;
    if (i < n) out[i] = pae[i];
}

// Per-edge ZBL energy, scattered with atomicAdd. 4 edges per thread.
__global__ void __launch_bounds__(256)
zbl_edge_kernel(const float* __restrict__ r,
                const int* __restrict__ types,
                const int* __restrict__ e_i,   // edge_index row 0 (segment target)
                const int* __restrict__ e_j,   // edge_index row 1
                const float* __restrict__ Z,
                float* __restrict__ out,
                int E)
{
    // Per-type-pair tables: exp args pre-multiplied by d_k*(Zi^p+Zj^p)/a0*log2e,
    // and the QQ*Zi*Zj prefactor.
    __shared__ float s_a1[16], s_a2[16], s_a3[16], s_a4[16], s_zzq[16];
    __shared__ float s_zp[4], s_z[4];

    const int tid = threadIdx.x;
    if (tid < 4) {
        float z = Z[tid];
        s_z[tid]  = z;
        s_zp[tid] = __powf(z, 0.23f);
    }
    __syncthreads();
    if (tid < 16) {
        int ti = tid >> 2, tj = tid & 3;
        float base = (s_zp[ti] + s_zp[tj]) * ZBL_INV_A0 * LOG2E;
        s_a1[tid] = -0.20162f * base;
        s_a2[tid] = -0.40290f * base;
        s_a3[tid] = -0.94229f * base;
        s_a4[tid] = -3.19980f * base;
        s_zzq[tid] = ZBL_QQ * s_z[ti] * s_z[tj];
    }
    __syncthreads();

    const int t = blockIdx.x * blockDim.x + tid;
    const int nvec = E >> 2;

    if (t < nvec) {
        // Front-batched vector loads: 1x float4 + 2x int4 (MLP = 3 wide loads).
        const float4 r4  = reinterpret_cast<const float4*>(r)[t];
        const int4   i4  = reinterpret_cast<const int4*>(e_i)[t];
        const int4   j4  = reinterpret_cast<const int4*>(e_j)[t];

        int   ii[4] = {i4.x, i4.y, i4.z, i4.w};
        int   jj[4] = {j4.x, j4.y, j4.z, j4.w};
        float rv[4] = {r4.x, r4.y, r4.z, r4.w};

        // Predicated type gathers: skip entirely for cut-off edges.
        bool live[4];
        int tiv[4], tjv[4];
        #pragma unroll
        for (int k = 0; k < 4; k++) {
            live[k] = rv[k] < 6.0f;
            tiv[k] = live[k] ? types[ii[k]] : 0;
            tjv[k] = live[k] ? types[jj[k]] : 0;
        }

        #pragma unroll
        for (int k = 0; k < 4; k++) {
            if (!live[k]) continue;
            const int p = (tiv[k] << 2) | tjv[k];
            const float rk = rv[k];

            // psi = sum c_m * exp(d_m * x); exp args fully folded into tables.
            const float e1 = ex2_approx(s_a1[p] * rk);
            const float e2 = ex2_approx(s_a2[p] * rk);
            const float e3 = ex2_approx(s_a3[p] * rk);
            const float e4 = ex2_approx(s_a4[p] * rk);
            float psi = fmaf(0.02817f, e1,
                        fmaf(0.28022f, e2,
                        fmaf(0.50986f, e3, 0.18175f * e4)));

            // Polynomial cutoff, p=6: 1 - 28 rr^6 + 48 rr^7 - 21 rr^8
            const float rr  = rk * ZBL_INV_RMAX;
            const float rr2 = rr * rr;
            const float rr3 = rr2 * rr;
            const float rr6 = rr3 * rr3;
            const float cut = fmaf(rr6, fmaf(rr, fmaf(rr, -21.0f, 48.0f), -28.0f), 1.0f);

            const float eng = s_zzq[p] * psi * rcp_approx(rk);
            atomicAdd(&out[ii[k]], eng * cut);
        }
    }

    // Scalar tail (E not divisible by 4): at most 3 edges, one thread.
    if (blockIdx.x == 0 && tid == 0) {
        for (int e = nvec << 2; e < E; e++) {
            float rk = r[e];
            if (rk >= 6.0f) continue;
            int i = e_i[e], j = e_j[e];
            int p = (types[i] << 2) | types[j];
            float e1 = ex2_approx(s_a1[p] * rk);
            float e2 = ex2_approx(s_a2[p] * rk);
            float e3 = ex2_approx(s_a3[p] * rk);
            float e4 = ex2_approx(s_a4[p] * rk);
            float psi = fmaf(0.02817f, e1,
                        fmaf(0.28022f, e2,
                        fmaf(0.50986f, e3, 0.18175f * e4)));
            float rr  = rk * ZBL_INV_RMAX;
            float rr2 = rr * rr;
            float rr6 = rr2 * rr2 * rr2;
            float cut = fmaf(rr6, fmaf(rr, fmaf(rr, -21.0f, 48.0f), -28.0f), 1.0f);
            float eng = s_zzq[p] * psi * rcp_approx(rk);
            atomicAdd(&out[i], eng * cut);
        }
    }
}

extern "C" void kernel_launch(void* const* d_in, const int* in_sizes, int n_in,
                              void* d_out, int out_size)
{
    const float* Z     = (const float*)d_in[0];
    const float* r     = (const float*)d_in[1];
    const float* pae   = (const float*)d_in[2];
    const int*   types = (const int*)d_in[3];
    const int*   eidx  = (const int*)d_in[4];
    float*       out   = (float*)d_out;

    const int E       = in_sizes[1];
    const int n_atoms = in_sizes[2];

    init_out_kernel<<<(n_atoms + 255) / 256, 256>>>(pae, out, n_atoms);

    int nvec = E >> 2;
    int blocks = (nvec + 255) / 256;
    if (blocks < 1) blocks = 1;  // tail-only case
    zbl_edge_kernel<<<blocks, 256>>>(r, types, eidx, eidx + E, Z, out, E);
}

// round 6
// speedup vs baseline: 1.2932x; 1.2932x over previous
#include <cuda_runtime.h>

// ZBL pair energy + segment-sum into per-atom energies.
//
// Inputs (metadata order; JAX default x64-off stores "int64" as int32):
//   d_in[0] Z               float32 [4]
//   d_in[1] r               float32 [E]          (E = 6,400,000)
//   d_in[2] per_atom_energy float32 [n_atoms,1]  (n_atoms = 100,000)
//   d_in[3] atom_types      int32   [n_atoms]
//   d_in[4] edge_index      int32   [2, E]
// Output: float32 [n_atoms, 1]
//
// Strategy: types are 2-bit (4 types). Pack 16 types/word -> 25KB table that
// lives in SHARED MEMORY, turning the 12.8M random L2 gathers into cheap LDS.

#define ZBL_QQ        7.1998225f        // 14.399645 * 0.5
#define ZBL_INV_A0    (1.0f / 0.4685f)
#define ZBL_INV_RMAX  (1.0f / 6.0f)
#define LOG2E         1.4426950408889634f

// Max atoms supported by the shared-memory LUT path: 6400 words * 16 = 102400.
#define SMEM_WORDS 6400
// Fallback global packed buffer: 1M words = 16M atoms (4MB static, allowed).
#define MAX_PACK_WORDS (1 << 20)
__device__ unsigned g_packed_types[MAX_PACK_WORDS];

__device__ __forceinline__ float ex2_approx(float x) {
    float y; asm("ex2.approx.f32 %0, %1;" : "=f"(y) : "f"(x)); return y;
}
__device__ __forceinline__ float rcp_approx(float x) {
    float y; asm("rcp.approx.f32 %0, %1;" : "=f"(y) : "f"(x)); return y;
}

__global__ void init_out_kernel(const float* __restrict__ pae,
                                float* __restrict__ out, int n) {
    int i = blockIdx.x * blockDim.x + threadIdx.x;
    if (i < n) out[i] = pae[i];
}

// Pack int32 types (values 0..3) into 2 bits each, 16 per word.
__global__ void pack_types_kernel(const int* __restrict__ types,
                                  int n_atoms, int n_words) {
    int w = blockIdx.x * blockDim.x + threadIdx.x;
    if (w >= n_words) return;
    unsigned v = 0;
    int base = w << 4;
    #pragma unroll
    for (int k = 0; k < 16; k++) {
        int a = base + k;
        unsigned t = (a < n_atoms) ? ((unsigned)types[a] & 3u) : 0u;
        v |= t << (k * 2);
    }
    g_packed_types[w] = v;
}

template <bool USE_SMEM>
__global__ void __launch_bounds__(256)
zbl_edge_kernel(const float* __restrict__ r,
                const int* __restrict__ e_i,   // edge_index row 0 (segment target)
                const int* __restrict__ e_j,   // edge_index row 1
                const float* __restrict__ Z,
                float* __restrict__ out,
                int E, int n_words)
{
    __shared__ unsigned s_pack[USE_SMEM ? SMEM_WORDS : 1];
    __shared__ float s_a1[16], s_a2[16], s_a3[16], s_a4[16], s_zzq[16];
    __shared__ float s_zp[4], s_z[4];

    const int tid = threadIdx.x;
    if (tid < 4) {
        float z = Z[tid];
        s_z[tid]  = z;
        s_zp[tid] = __powf(z, 0.23f);
    }
    __syncthreads();
    if (tid < 16) {
        int ti = tid >> 2, tj = tid & 3;
        float base = (s_zp[ti] + s_zp[tj]) * ZBL_INV_A0 * LOG2E;
        s_a1[tid] = -0.20162f * base;
        s_a2[tid] = -0.40290f * base;
        s_a3[tid] = -0.94229f * base;
        s_a4[tid] = -3.19980f * base;
        s_zzq[tid] = ZBL_QQ * s_z[ti] * s_z[tj];
    }
    if (USE_SMEM) {
        for (int w = tid; w < n_words; w += 256)
            s_pack[w] = g_packed_types[w];
    }
    __syncthreads();

    const unsigned* __restrict__ tbl = USE_SMEM ? s_pack : g_packed_types;

    const int nvec   = E >> 2;
    const int stride = gridDim.x * blockDim.x;

    for (int t = blockIdx.x * blockDim.x + tid; t < nvec; t += stride) {
        const float4 r4 = __ldg(reinterpret_cast<const float4*>(r) + t);
        const int4   i4 = __ldg(reinterpret_cast<const int4*>(e_i) + t);
        const int4   j4 = __ldg(reinterpret_cast<const int4*>(e_j) + t);

        int   ii[4] = {i4.x, i4.y, i4.z, i4.w};
        int   jj[4] = {j4.x, j4.y, j4.z, j4.w};
        float rv[4] = {r4.x, r4.y, r4.z, r4.w};

        #pragma unroll
        for (int k = 0; k < 4; k++) {
            const float rk = rv[k];
            const bool live = rk < 6.0f;
            if (!live) continue;

            // 2-bit type lookup from shared (or L1-cached global) packed table.
            const unsigned wi = tbl[ii[k] >> 4];
            const unsigned wj = tbl[jj[k] >> 4];
            const int ti = (wi >> ((ii[k] & 15) << 1)) & 3;
            const int tj = (wj >> ((jj[k] & 15) << 1)) & 3;
            const int p  = (ti << 2) | tj;

            // psi = sum c_m * exp(d_m * x); exp args fully folded into tables.
            const float e1 = ex2_approx(s_a1[p] * rk);
            const float e2 = ex2_approx(s_a2[p] * rk);
            const float e3 = ex2_approx(s_a3[p] * rk);
            const float e4 = ex2_approx(s_a4[p] * rk);
            float psi = fmaf(0.02817f, e1,
                        fmaf(0.28022f, e2,
                        fmaf(0.50986f, e3, 0.18175f * e4)));

            // Polynomial cutoff, p=6: 1 - 28 rr^6 + 48 rr^7 - 21 rr^8
            const float rr  = rk * ZBL_INV_RMAX;
            const float rr2 = rr * rr;
            const float rr3 = rr2 * rr;
            const float rr6 = rr3 * rr3;
            const float cut = fmaf(rr6, fmaf(rr, fmaf(rr, -21.0f, 48.0f), -28.0f), 1.0f);

            const float eng = s_zzq[p] * psi * rcp_approx(rk);
            atomicAdd(&out[ii[k]], eng * cut);
        }
    }

    // Scalar tail (E not divisible by 4): at most 3 edges, one thread.
    if (blockIdx.x == 0 && tid == 0) {
        for (int e = nvec << 2; e < E; e++) {
            float rk = r[e];
            if (rk >= 6.0f) continue;
            int i = e_i[e], j = e_j[e];
            unsigned wi = tbl[i >> 4];
            unsigned wj = tbl[j >> 4];
            int ti = (wi >> ((i & 15) << 1)) & 3;
            int tj = (wj >> ((j & 15) << 1)) & 3;
            int p = (ti << 2) | tj;
            float e1 = ex2_approx(s_a1[p] * rk);
            float e2 = ex2_approx(s_a2[p] * rk);
            float e3 = ex2_approx(s_a3[p] * rk);
            float e4 = ex2_approx(s_a4[p] * rk);
            float psi = fmaf(0.02817f, e1,
                        fmaf(0.28022f, e2,
                        fmaf(0.50986f, e3, 0.18175f * e4)));
            float rr  = rk * ZBL_INV_RMAX;
            float rr2 = rr * rr;
            float rr6 = rr2 * rr2 * rr2;
            float cut = fmaf(rr6, fmaf(rr, fmaf(rr, -21.0f, 48.0f), -28.0f), 1.0f);
            float eng = s_zzq[p] * psi * rcp_approx(rk);
            atomicAdd(&out[i], eng * cut);
        }
    }
}

extern "C" void kernel_launch(void* const* d_in, const int* in_sizes, int n_in,
                              void* d_out, int out_size)
{
    const float* Z     = (const float*)d_in[0];
    const float* r     = (const float*)d_in[1];
    const float* pae   = (const float*)d_in[2];
    const int*   types = (const int*)d_in[3];
    const int*   eidx  = (const int*)d_in[4];
    float*       out   = (float*)d_out;

    const int E       = in_sizes[1];
    const int n_atoms = in_sizes[2];
    const int n_words = (n_atoms + 15) >> 4;

    init_out_kernel<<<(n_atoms + 255) / 256, 256>>>(pae, out, n_atoms);
    pack_types_kernel<<<(n_words + 127) / 128, 128>>>(types, n_atoms, n_words);

    // Persistent-style grid: 8 blocks/SM (26KB smem each) x ~152 SMs.
    const int blocks = 1216;
    if (n_words <= SMEM_WORDS) {
        zbl_edge_kernel<true><<<blocks, 256>>>(r, eidx, eidx + E, Z, out, E, n_words);
    } else {
        zbl_edge_kernel<false><<<blocks, 256>>>(r, eidx, eidx + E, Z, out, E, n_words);
    }
}